// round 2
// baseline (speedup 1.0000x reference)
#include <cuda_runtime.h>
#include <math.h>

// DeFeat distillation loss, fused per-level: adapted = W @ feat_s (+bias),
// masked squared diff vs feat_t, deterministic two-stage reduction.
// B=8, C=256, sizes {128,64,32,16,8}, strides {8,16,32,64,128}, N=16 boxes.

#define CC   256
#define NBOX 16
#define BM   64
#define BN   64
#define BK   16

// Partial sums per block, fixed slots -> fully deterministic.
// Total blocks = 8192+2048+512+128+32 = 10912.
__device__ float g_part_gt[11008];
__device__ float g_part_bg[11008];

__global__ __launch_bounds__(256, 4)
void defeat_level_kernel(const float* __restrict__ fs,
                         const float* __restrict__ ft,
                         const float* __restrict__ Wm,
                         const float* __restrict__ bias,
                         const float* __restrict__ boxes,  // [B,16,4]
                         int H, int Wd, int stride, int partBase)
{
    __shared__ float As[BK][BM];       // W tile, transposed: As[k][m]
    __shared__ float Bs[BK][BN];       // feat_s tile
    __shared__ float mask_s[BN];
    __shared__ float boxes_s[NBOX * 4];
    __shared__ float red[16];

    const int tid     = threadIdx.x;
    const int b       = blockIdx.z;
    const int mBase   = blockIdx.y * BM;
    const int posBase = blockIdx.x * BN;
    const int HWp     = H * Wd;

    if (tid < NBOX * 4)
        boxes_s[tid] = boxes[(size_t)b * NBOX * 4 + tid];
    __syncthreads();

    // Rasterize GT mask for this block's 64 spatial positions.
    if (tid < BN) {
        int pos = posBase + tid;
        int y = pos / Wd, x = pos % Wd;
        float m = 0.f;
        #pragma unroll 1
        for (int n = 0; n < NBOX; n++) {
            float inv = 1.0f / (float)stride;
            int lx = min((int)floorf(boxes_s[n*4+0] * inv), Wd - 1);
            int ly = min((int)floorf(boxes_s[n*4+1] * inv), H  - 1);
            int rx = min((int)floorf(boxes_s[n*4+2] * inv), Wd - 1);
            int ry = min((int)floorf(boxes_s[n*4+3] * inv), H  - 1);
            bool hit;
            if (lx == rx || ly == ry) hit = (y == ly) && (x == lx);   // degenerate -> single pixel
            else                      hit = (y >= ly) && (y < ry) && (x >= lx) && (x < rx);
            if (hit) { m = 1.f; break; }
        }
        mask_s[tid] = m;
    }

    const int ty = tid >> 4;       // 0..15  (M sub-tile)
    const int tx = tid & 15;       // 0..15  (N sub-tile)
    float acc[4][4] = {};
    const float* fsb = fs + (size_t)b * CC * HWp;

    for (int k0 = 0; k0 < CC; k0 += BK) {
        // Load W tile [BM x BK] -> transposed As[BK][BM]
        {
            int r  = tid >> 2;              // 0..63
            int c4 = (tid & 3) * 4;         // 0,4,8,12
            float4 v = *(const float4*)&Wm[(size_t)(mBase + r) * CC + k0 + c4];
            As[c4 + 0][r] = v.x; As[c4 + 1][r] = v.y;
            As[c4 + 2][r] = v.z; As[c4 + 3][r] = v.w;
        }
        // Load feat_s tile [BK x BN] (coalesced float4)
        {
            int r  = tid >> 4;              // 0..15
            int c4 = (tid & 15) * 4;        // 0..60
            *(float4*)&Bs[r][c4] =
                *(const float4*)&fsb[(size_t)(k0 + r) * HWp + posBase + c4];
        }
        __syncthreads();

        #pragma unroll
        for (int k = 0; k < BK; k++) {
            float4 a4 = *(const float4*)&As[k][ty * 4];
            float4 b4 = *(const float4*)&Bs[k][tx * 4];
            float av[4] = {a4.x, a4.y, a4.z, a4.w};
            float bv[4] = {b4.x, b4.y, b4.z, b4.w};
            #pragma unroll
            for (int i = 0; i < 4; i++)
                #pragma unroll
                for (int j = 0; j < 4; j++)
                    acc[i][j] += av[i] * bv[j];
        }
        __syncthreads();
    }

    // Epilogue: masked squared diff against feat_t.
    float sgt = 0.f, sbg = 0.f;
    const float* ftb = ft + (size_t)b * CC * HWp;
    #pragma unroll
    for (int i = 0; i < 4; i++) {
        int row = mBase + ty * 4 + i;
        float bv = bias[row];
        float4 t4 = *(const float4*)&ftb[(size_t)row * HWp + posBase + tx * 4];
        float tv[4] = {t4.x, t4.y, t4.z, t4.w};
        #pragma unroll
        for (int j = 0; j < 4; j++) {
            float d  = tv[j] - (acc[i][j] + bv);
            float d2 = d * d;
            float m  = mask_s[tx * 4 + j];
            sgt += d2 * m;
            sbg += d2 * (1.f - m);
        }
    }

    // Deterministic block reduction: warp shuffle + fixed-order smem sum.
    #pragma unroll
    for (int off = 16; off > 0; off >>= 1) {
        sgt += __shfl_down_sync(0xffffffffu, sgt, off);
        sbg += __shfl_down_sync(0xffffffffu, sbg, off);
    }
    int warp = tid >> 5, lane = tid & 31;
    if (lane == 0) { red[warp] = sgt; red[warp + 8] = sbg; }
    __syncthreads();
    if (tid == 0) {
        float g = 0.f, bg = 0.f;
        #pragma unroll
        for (int w2 = 0; w2 < 8; w2++) { g += red[w2]; bg += red[w2 + 8]; }
        int linear = (blockIdx.z * gridDim.y + blockIdx.y) * gridDim.x + blockIdx.x;
        g_part_gt[partBase + linear] = g;
        g_part_bg[partBase + linear] = bg;
    }
}

__global__ void defeat_finalize_kernel(float* __restrict__ out)
{
    __shared__ float red[256];
    __shared__ float loss_s;
    const int counts[5] = {8192, 2048, 512, 128, 32};
    const int tid = threadIdx.x;
    if (tid == 0) loss_s = 0.f;
    __syncthreads();
    int off = 0;
    for (int lvl = 0; lvl < 5; lvl++) {
        float g = 0.f, bg = 0.f;
        for (int i = tid; i < counts[lvl]; i += 256) g  += g_part_gt[off + i];
        for (int i = tid; i < counts[lvl]; i += 256) bg += g_part_bg[off + i];

        red[tid] = g; __syncthreads();
        for (int s = 128; s > 0; s >>= 1) { if (tid < s) red[tid] += red[tid + s]; __syncthreads(); }
        float gs = red[0]; __syncthreads();

        red[tid] = bg; __syncthreads();
        for (int s = 128; s > 0; s >>= 1) { if (tid < s) red[tid] += red[tid + s]; __syncthreads(); }
        float bgs = red[0]; __syncthreads();

        if (tid == 0)
            loss_s += 0.004f * sqrtf(gs + 1e-8f) + 0.0002f * sqrtf(bgs + 1e-8f);
        off += counts[lvl];
        __syncthreads();
    }
    if (tid == 0) out[0] = loss_s;
}

extern "C" void kernel_launch(void* const* d_in, const int* in_sizes, int n_in,
                              void* d_out, int out_size)
{
    (void)in_sizes; (void)n_in; (void)out_size;
    const int SIZES[5] = {128, 64, 32, 16, 8};
    const int STR[5]   = {8, 16, 32, 64, 128};
    const float* boxes = (const float*)d_in[20];

    int partBase = 0;
    for (int i = 0; i < 5; i++) {
        const float* fs = (const float*)d_in[4 * i + 0];
        const float* ft = (const float*)d_in[4 * i + 1];
        const float* Wm = (const float*)d_in[4 * i + 2];
        const float* bv = (const float*)d_in[4 * i + 3];
        int H  = SIZES[i];
        int HW = H * H;
        dim3 grid(HW / BN, CC / BM, 8);
        defeat_level_kernel<<<grid, 256>>>(fs, ft, Wm, bv, boxes, H, H, STR[i], partBase);
        partBase += grid.x * grid.y * grid.z;
    }
    defeat_finalize_kernel<<<1, 256>>>((float*)d_out);
}

// round 3
// speedup vs baseline: 2.2728x; 2.2728x over previous
#include <cuda_runtime.h>
#include <math.h>
#include <stdint.h>

// DeFeat distillation loss, all 5 levels fused into ONE launch.
// adapted = W @ feat_s (+bias) via tf32 mma.sync, masked squared diff vs feat_t,
// deterministic reduction. B=8, C=256, sizes {128,64,32,16,8}, strides {8..128}.

#define CC   256
#define NBOX 16
#define BM   128
#define BN   64
#define BK   32

// Block counts per level: 4096,1024,256,64,16 -> 5456 total
__device__ float g_part_gt[5504];
__device__ float g_part_bg[5504];

struct LevelPtrs { const float *fs, *ft, *Wm, *bias; };
struct KP { LevelPtrs lv[5]; const float* boxes; };

__device__ __forceinline__ uint32_t f2tf(float x) {
    uint32_t r;
    asm("cvt.rna.tf32.f32 %0, %1;" : "=r"(r) : "f"(x));
    return r;
}

__device__ __forceinline__ void mma_tf32(float c[4], const uint32_t a[4], const uint32_t b[2]) {
    asm volatile(
        "mma.sync.aligned.m16n8k8.row.col.f32.tf32.tf32.f32 "
        "{%0,%1,%2,%3}, {%4,%5,%6,%7}, {%8,%9}, {%0,%1,%2,%3};\n"
        : "+f"(c[0]), "+f"(c[1]), "+f"(c[2]), "+f"(c[3])
        : "r"(a[0]), "r"(a[1]), "r"(a[2]), "r"(a[3]), "r"(b[0]), "r"(b[1]));
}

__global__ __launch_bounds__(256)
void defeat_fused_kernel(KP P)
{
    // Row strides 136 and 72 are both ≡ 8 (mod 32) -> fragment LDS conflict-free.
    __shared__ uint32_t Ast[BK][136];   // W tile transposed: Ast[k][m] (tf32 bits)
    __shared__ uint32_t Bs[BK][72];     // feat_s tile: Bs[k][n]
    __shared__ float mask_s[BN];
    __shared__ float boxes_s[NBOX * 4];
    __shared__ float red[16];

    const int tid = threadIdx.x;
    const int bid = blockIdx.x;

    // ---- decode level + tile ----
    int lvl, base;
    if      (bid < 4096) { lvl = 0; base = 0;    }
    else if (bid < 5120) { lvl = 1; base = 4096; }
    else if (bid < 5376) { lvl = 2; base = 5120; }
    else if (bid < 5440) { lvl = 3; base = 5376; }
    else                 { lvl = 4; base = 5440; }

    const int H      = 128 >> lvl;
    const int stride = 8 << lvl;
    const int HW     = H * H;
    const int nTN    = HW >> 6;           // spatial tiles of 64

    int rel   = bid - base;
    int b     = rel / (nTN * 2);
    int r2    = rel - b * (nTN * 2);
    int mTile = r2 / nTN;
    int nTile = r2 - mTile * nTN;
    const int mBase   = mTile * BM;
    const int posBase = nTile * BN;

    const float* fsb  = P.lv[lvl].fs   + (size_t)b * CC * HW;
    const float* ftb  = P.lv[lvl].ft   + (size_t)b * CC * HW;
    const float* Wm   = P.lv[lvl].Wm;
    const float* bias = P.lv[lvl].bias;

    if (tid < NBOX * 4)
        boxes_s[tid] = P.boxes[(size_t)b * NBOX * 4 + tid];
    __syncthreads();

    // ---- rasterize GT mask for this block's 64 positions ----
    if (tid < BN) {
        int pos = posBase + tid;
        int y = pos / H, x = pos - y * H;
        float m = 0.f;
        float inv = 1.0f / (float)stride;
        #pragma unroll 1
        for (int n = 0; n < NBOX; n++) {
            int lx = min((int)floorf(boxes_s[n*4+0] * inv), H - 1);
            int ly = min((int)floorf(boxes_s[n*4+1] * inv), H - 1);
            int rx = min((int)floorf(boxes_s[n*4+2] * inv), H - 1);
            int ry = min((int)floorf(boxes_s[n*4+3] * inv), H - 1);
            bool hit;
            if (lx == rx || ly == ry) hit = (y == ly) && (x == lx);
            else                      hit = (y >= ly) && (y < ry) && (x >= lx) && (x < rx);
            if (hit) { m = 1.f; break; }
        }
        mask_s[tid] = m;
    }

    // ---- warp layout: 8 warps = 4(m) x 2(n), each warp 32x32 ----
    const int warp = tid >> 5, lane = tid & 31;
    const int wm = warp >> 1, wn = warp & 1;
    const int gid = lane >> 2, tg = lane & 3;     // mma group / thread-in-group
    const int M0 = wm * 32;                       // warp m offset in tile
    const int N0 = wn * 32;                       // warp n offset in tile

    float acc[2][4][4];
    #pragma unroll
    for (int mt = 0; mt < 2; mt++)
        #pragma unroll
        for (int nt = 0; nt < 4; nt++)
            #pragma unroll
            for (int r = 0; r < 4; r++) acc[mt][nt][r] = 0.f;

    for (int k0 = 0; k0 < CC; k0 += BK) {
        // Load W tile [BM x BK] -> transposed Ast[k][m], tf32
        {
            int m  = tid >> 1;
            int kq = (tid & 1) * 16;
            const float* wrow = Wm + (size_t)(mBase + m) * CC + k0 + kq;
            #pragma unroll
            for (int j = 0; j < 4; j++) {
                float4 v = *(const float4*)(wrow + 4 * j);
                Ast[kq + 4*j + 0][m] = f2tf(v.x);
                Ast[kq + 4*j + 1][m] = f2tf(v.y);
                Ast[kq + 4*j + 2][m] = f2tf(v.z);
                Ast[kq + 4*j + 3][m] = f2tf(v.w);
            }
        }
        // Load feat_s tile [BK x BN], tf32
        {
            int kk = tid >> 4;
            int n4 = (tid & 15) * 4;
            #pragma unroll
            for (int h = 0; h < 2; h++) {
                int kr = kk + 16 * h;
                float4 v = *(const float4*)&fsb[(size_t)(k0 + kr) * HW + posBase + n4];
                uint4 u;
                u.x = f2tf(v.x); u.y = f2tf(v.y); u.z = f2tf(v.z); u.w = f2tf(v.w);
                *(uint4*)&Bs[kr][n4] = u;
            }
        }
        __syncthreads();

        #pragma unroll
        for (int ks = 0; ks < BK; ks += 8) {
            uint32_t afr[2][4], bfr[4][2];
            #pragma unroll
            for (int mt = 0; mt < 2; mt++) {
                int mr = M0 + mt * 16 + gid;
                afr[mt][0] = Ast[ks + tg    ][mr    ];
                afr[mt][1] = Ast[ks + tg    ][mr + 8];
                afr[mt][2] = Ast[ks + tg + 4][mr    ];
                afr[mt][3] = Ast[ks + tg + 4][mr + 8];
            }
            #pragma unroll
            for (int nt = 0; nt < 4; nt++) {
                int nc = N0 + nt * 8 + gid;
                bfr[nt][0] = Bs[ks + tg    ][nc];
                bfr[nt][1] = Bs[ks + tg + 4][nc];
            }
            #pragma unroll
            for (int mt = 0; mt < 2; mt++)
                #pragma unroll
                for (int nt = 0; nt < 4; nt++)
                    mma_tf32(acc[mt][nt], afr[mt], bfr[nt]);
        }
        __syncthreads();
    }

    // ---- epilogue: masked squared diff vs feat_t ----
    float sgt = 0.f, sbg = 0.f;
    #pragma unroll
    for (int mt = 0; mt < 2; mt++) {
        #pragma unroll
        for (int h = 0; h < 2; h++) {
            int rowL = M0 + mt * 16 + gid + 8 * h;
            int row  = mBase + rowL;
            float bv = bias[row];
            #pragma unroll
            for (int nt = 0; nt < 4; nt++) {
                int colL = N0 + nt * 8 + 2 * tg;
                float2 t2 = *(const float2*)&ftb[(size_t)row * HW + posBase + colL];
                float a0 = acc[mt][nt][2*h + 0] + bv;
                float a1 = acc[mt][nt][2*h + 1] + bv;
                float d0 = t2.x - a0, d1 = t2.y - a1;
                float m0 = mask_s[colL], m1 = mask_s[colL + 1];
                float q0 = d0 * d0, q1 = d1 * d1;
                sgt += q0 * m0 + q1 * m1;
                sbg += q0 * (1.f - m0) + q1 * (1.f - m1);
            }
        }
    }

    // ---- deterministic block reduction ----
    #pragma unroll
    for (int off = 16; off > 0; off >>= 1) {
        sgt += __shfl_down_sync(0xffffffffu, sgt, off);
        sbg += __shfl_down_sync(0xffffffffu, sbg, off);
    }
    if (lane == 0) { red[warp] = sgt; red[warp + 8] = sbg; }
    __syncthreads();
    if (tid == 0) {
        float g = 0.f, bg = 0.f;
        #pragma unroll
        for (int w2 = 0; w2 < 8; w2++) { g += red[w2]; bg += red[w2 + 8]; }
        g_part_gt[bid] = g;
        g_part_bg[bid] = bg;
    }
}

__global__ void defeat_finalize_kernel(float* __restrict__ out)
{
    __shared__ float red[256];
    __shared__ float loss_s;
    const int counts[5] = {4096, 1024, 256, 64, 16};
    const int tid = threadIdx.x;
    if (tid == 0) loss_s = 0.f;
    __syncthreads();
    int off = 0;
    for (int lvl = 0; lvl < 5; lvl++) {
        float g = 0.f, bg = 0.f;
        for (int i = tid; i < counts[lvl]; i += 256) g  += g_part_gt[off + i];
        for (int i = tid; i < counts[lvl]; i += 256) bg += g_part_bg[off + i];

        red[tid] = g; __syncthreads();
        for (int s = 128; s > 0; s >>= 1) { if (tid < s) red[tid] += red[tid + s]; __syncthreads(); }
        float gs = red[0]; __syncthreads();

        red[tid] = bg; __syncthreads();
        for (int s = 128; s > 0; s >>= 1) { if (tid < s) red[tid] += red[tid + s]; __syncthreads(); }
        float bgs = red[0]; __syncthreads();

        if (tid == 0)
            loss_s += 0.004f * sqrtf(gs + 1e-8f) + 0.0002f * sqrtf(bgs + 1e-8f);
        off += counts[lvl];
        __syncthreads();
    }
    if (tid == 0) out[0] = loss_s;
}

extern "C" void kernel_launch(void* const* d_in, const int* in_sizes, int n_in,
                              void* d_out, int out_size)
{
    (void)in_sizes; (void)n_in; (void)out_size;
    KP P;
    for (int i = 0; i < 5; i++) {
        P.lv[i].fs   = (const float*)d_in[4 * i + 0];
        P.lv[i].ft   = (const float*)d_in[4 * i + 1];
        P.lv[i].Wm   = (const float*)d_in[4 * i + 2];
        P.lv[i].bias = (const float*)d_in[4 * i + 3];
    }
    P.boxes = (const float*)d_in[20];

    defeat_fused_kernel<<<5456, 256>>>(P);
    defeat_finalize_kernel<<<1, 256>>>((float*)d_out);
}

// round 5
// speedup vs baseline: 3.6635x; 1.6119x over previous
#include <cuda_runtime.h>
#include <math.h>
#include <stdint.h>

// DeFeat distillation loss. One fused tf32-MMA kernel for all 5 levels.
// W pre-converted to tf32 + pre-transposed; feat_s fed as truncated tf32.
// B=8, C=256, sizes {128,64,32,16,8}, strides {8..128}, 16 boxes.

#define CC   256
#define NBOX 16
#define BM   256
#define BN   64
#define BK   16
#define NIT  (CC / BK)      // 16
#define APAD 264            // A smem row stride (k-major), 264 % 32 == 8
#define BPAD 72             // B smem row stride,            72 % 32 == 8

// Blocks per level: 2048,512,128,32,8 -> 2728
__device__ float g_part_gt[2752];
__device__ float g_part_bg[2752];
__device__ uint32_t g_Wt[5][CC * CC];   // tf32 bits, [lvl][k][m]

struct LevelPtrs { const float *fs, *ft, *Wm, *bias; };
struct KP { LevelPtrs lv[5]; const float* boxes; };

__device__ __forceinline__ uint32_t f2tf(float x) {
    uint32_t r;
    asm("cvt.rna.tf32.f32 %0, %1;" : "=r"(r) : "f"(x));
    return r;
}

__device__ __forceinline__ void cp16(void* smem_dst, const void* gmem_src) {
    uint32_t d = (uint32_t)__cvta_generic_to_shared(smem_dst);
    asm volatile("cp.async.cg.shared.global [%0], [%1], 16;\n" :: "r"(d), "l"(gmem_src));
}
__device__ __forceinline__ void cp_commit() {
    asm volatile("cp.async.commit_group;\n");
}
template<int N> __device__ __forceinline__ void cp_wait() {
    asm volatile("cp.async.wait_group %0;\n" :: "n"(N));
}

__device__ __forceinline__ void mma_tf32(float c[4], const uint32_t a[4], const uint32_t b[2]) {
    asm volatile(
        "mma.sync.aligned.m16n8k8.row.col.f32.tf32.tf32.f32 "
        "{%0,%1,%2,%3}, {%4,%5,%6,%7}, {%8,%9}, {%0,%1,%2,%3};\n"
        : "+f"(c[0]), "+f"(c[1]), "+f"(c[2]), "+f"(c[3])
        : "r"(a[0]), "r"(a[1]), "r"(a[2]), "r"(a[3]), "r"(b[0]), "r"(b[1]));
}

// ---- W prep: transpose + cvt to tf32. W[m][k] -> Wt[k][m]. grid (8,8,5), block (32,8)
__global__ void defeat_prep_kernel(KP P)
{
    __shared__ float tile[32][33];
    int lvl = blockIdx.z;
    const float* Wm = P.lv[lvl].Wm;
    int bx = blockIdx.x * 32, by = blockIdx.y * 32;
    int tx = threadIdx.x, ty = threadIdx.y;
    #pragma unroll
    for (int i = 0; i < 32; i += 8)
        tile[ty + i][tx] = Wm[(size_t)(by + ty + i) * CC + bx + tx];
    __syncthreads();
    #pragma unroll
    for (int i = 0; i < 32; i += 8)
        g_Wt[lvl][(size_t)(bx + ty + i) * CC + by + tx] = f2tf(tile[tx][ty + i]);
}

__global__ __launch_bounds__(256, 2)
void defeat_fused_kernel(KP P)
{
    __shared__ uint32_t As[2][BK * APAD];   // Wt tile, [k][m]
    __shared__ uint32_t Bs[2][BK * BPAD];   // feat_s tile, [k][n] (raw fp32 bits)
    __shared__ float mask_s[BN];
    __shared__ float boxes_s[NBOX * 4];
    __shared__ float red[16];

    const int tid = threadIdx.x;
    const int bid = blockIdx.x;

    // ---- decode level + tile ----
    int lvl, base;
    if      (bid < 2048) { lvl = 0; base = 0;    }
    else if (bid < 2560) { lvl = 1; base = 2048; }
    else if (bid < 2688) { lvl = 2; base = 2560; }
    else if (bid < 2720) { lvl = 3; base = 2688; }
    else                 { lvl = 4; base = 2720; }

    const int H      = 128 >> lvl;
    const int stride = 8 << lvl;
    const int HW     = H * H;
    const int nTN    = HW >> 6;

    int rel   = bid - base;
    int b     = rel / nTN;
    int nTile = rel - b * nTN;
    const int posBase = nTile * BN;

    const float* fsb  = P.lv[lvl].fs + (size_t)b * CC * HW;
    const float* ftb  = P.lv[lvl].ft + (size_t)b * CC * HW;
    const float* bias = P.lv[lvl].bias;
    const uint32_t* WtL = g_Wt[lvl];

    if (tid < NBOX * 4)
        boxes_s[tid] = P.boxes[(size_t)b * NBOX * 4 + tid];
    __syncthreads();

    if (tid < BN) {
        int pos = posBase + tid;
        int y = pos / H, x = pos - y * H;
        float m = 0.f;
        float inv = 1.0f / (float)stride;
        #pragma unroll 1
        for (int n = 0; n < NBOX; n++) {
            int lx = min((int)floorf(boxes_s[n*4+0] * inv), H - 1);
            int ly = min((int)floorf(boxes_s[n*4+1] * inv), H - 1);
            int rx = min((int)floorf(boxes_s[n*4+2] * inv), H - 1);
            int ry = min((int)floorf(boxes_s[n*4+3] * inv), H - 1);
            bool hit;
            if (lx == rx || ly == ry) hit = (y == ly) && (x == lx);
            else                      hit = (y >= ly) && (y < ry) && (x >= lx) && (x < rx);
            if (hit) { m = 1.f; break; }
        }
        mask_s[tid] = m;
    }

    // ---- tile loaders (cp.async) ----
    // A: BK x 256 floats = 1024 chunks of 16B -> 4/thread
    // B: BK x 64  floats = 256 chunks         -> 1/thread
    const int aRow = tid >> 6;           // reused: c = tid + i*256 -> row = c>>6
    const int aCol = (tid & 63) * 4;
    const int bRow = tid >> 4;
    const int bCol = (tid & 15) * 4;

    auto issue = [&](int k0, int buf) {
        #pragma unroll
        for (int i = 0; i < 4; i++) {
            int row = aRow + i * 4;      // (tid + i*256) >> 6 = aRow + 4i
            cp16(&As[buf][row * APAD + aCol], WtL + (size_t)(k0 + row) * CC + aCol);
        }
        cp16(&Bs[buf][bRow * BPAD + bCol], fsb + (size_t)(k0 + bRow) * HW + posBase + bCol);
    };

    // ---- warp layout: 8 warps = 4(m) x 2(n); warp tile 64m x 32n ----
    const int warp = tid >> 5, lane = tid & 31;
    const int wm = warp >> 1, wn = warp & 1;
    const int gid = lane >> 2, tg = lane & 3;
    const int M0 = wm * 64;
    const int N0 = wn * 32;

    float acc[4][4][4];
    #pragma unroll
    for (int mt = 0; mt < 4; mt++)
        #pragma unroll
        for (int nt = 0; nt < 4; nt++)
            #pragma unroll
            for (int r = 0; r < 4; r++) acc[mt][nt][r] = 0.f;

    issue(0, 0);
    cp_commit();

    for (int it = 0; it < NIT; it++) {
        if (it + 1 < NIT) { issue((it + 1) * BK, (it + 1) & 1); cp_commit(); cp_wait<1>(); }
        else              { cp_wait<0>(); }
        __syncthreads();

        const int buf = it & 1;
        #pragma unroll
        for (int ks = 0; ks < BK; ks += 8) {
            uint32_t afr[4][4], bfr[4][2];
            #pragma unroll
            for (int mt = 0; mt < 4; mt++) {
                int mr = M0 + mt * 16 + gid;
                afr[mt][0] = As[buf][(ks + tg    ) * APAD + mr    ];
                afr[mt][1] = As[buf][(ks + tg    ) * APAD + mr + 8];
                afr[mt][2] = As[buf][(ks + tg + 4) * APAD + mr    ];
                afr[mt][3] = As[buf][(ks + tg + 4) * APAD + mr + 8];
            }
            #pragma unroll
            for (int nt = 0; nt < 4; nt++) {
                int nc = N0 + nt * 8 + gid;
                bfr[nt][0] = Bs[buf][(ks + tg    ) * BPAD + nc];
                bfr[nt][1] = Bs[buf][(ks + tg + 4) * BPAD + nc];
            }
            #pragma unroll
            for (int mt = 0; mt < 4; mt++)
                #pragma unroll
                for (int nt = 0; nt < 4; nt++)
                    mma_tf32(acc[mt][nt], afr[mt], bfr[nt]);
        }
        __syncthreads();
    }

    // ---- epilogue: masked squared diff vs feat_t ----
    float sgt = 0.f, sbg = 0.f;
    #pragma unroll
    for (int mt = 0; mt < 4; mt++) {
        #pragma unroll
        for (int h = 0; h < 2; h++) {
            int row = M0 + mt * 16 + gid + 8 * h;
            float bv = bias[row];
            #pragma unroll
            for (int nt = 0; nt < 4; nt++) {
                int colL = N0 + nt * 8 + 2 * tg;
                float2 t2 = *(const float2*)&ftb[(size_t)row * HW + posBase + colL];
                float a0 = acc[mt][nt][2*h + 0] + bv;
                float a1 = acc[mt][nt][2*h + 1] + bv;
                float d0 = t2.x - a0, d1 = t2.y - a1;
                float m0 = mask_s[colL], m1 = mask_s[colL + 1];
                float q0 = d0 * d0, q1 = d1 * d1;
                sgt += q0 * m0 + q1 * m1;
                sbg += q0 * (1.f - m0) + q1 * (1.f - m1);
            }
        }
    }

    #pragma unroll
    for (int off = 16; off > 0; off >>= 1) {
        sgt += __shfl_down_sync(0xffffffffu, sgt, off);
        sbg += __shfl_down_sync(0xffffffffu, sbg, off);
    }
    if (lane == 0) { red[warp] = sgt; red[warp + 8] = sbg; }
    __syncthreads();
    if (tid == 0) {
        float g = 0.f, bg = 0.f;
        #pragma unroll
        for (int w2 = 0; w2 < 8; w2++) { g += red[w2]; bg += red[w2 + 8]; }
        g_part_gt[bid] = g;
        g_part_bg[bid] = bg;
    }
}

__global__ void defeat_finalize_kernel(float* __restrict__ out)
{
    __shared__ float red[256];
    __shared__ float loss_s;
    const int counts[5] = {2048, 512, 128, 32, 8};
    const int tid = threadIdx.x;
    if (tid == 0) loss_s = 0.f;
    __syncthreads();
    int off = 0;
    for (int lvl = 0; lvl < 5; lvl++) {
        float g = 0.f, bg = 0.f;
        for (int i = tid; i < counts[lvl]; i += 256) g  += g_part_gt[off + i];
        for (int i = tid; i < counts[lvl]; i += 256) bg += g_part_bg[off + i];

        red[tid] = g; __syncthreads();
        for (int s = 128; s > 0; s >>= 1) { if (tid < s) red[tid] += red[tid + s]; __syncthreads(); }
        float gs = red[0]; __syncthreads();

        red[tid] = bg; __syncthreads();
        for (int s = 128; s > 0; s >>= 1) { if (tid < s) red[tid] += red[tid + s]; __syncthreads(); }
        float bgs = red[0]; __syncthreads();

        if (tid == 0)
            loss_s += 0.004f * sqrtf(gs + 1e-8f) + 0.0002f * sqrtf(bgs + 1e-8f);
        off += counts[lvl];
        __syncthreads();
    }
    if (tid == 0) out[0] = loss_s;
}

extern "C" void kernel_launch(void* const* d_in, const int* in_sizes, int n_in,
                              void* d_out, int out_size)
{
    (void)in_sizes; (void)n_in; (void)out_size;
    KP P;
    for (int i = 0; i < 5; i++) {
        P.lv[i].fs   = (const float*)d_in[4 * i + 0];
        P.lv[i].ft   = (const float*)d_in[4 * i + 1];
        P.lv[i].Wm   = (const float*)d_in[4 * i + 2];
        P.lv[i].bias = (const float*)d_in[4 * i + 3];
    }
    P.boxes = (const float*)d_in[20];

    dim3 pgrid(8, 8, 5), pblk(32, 8);
    defeat_prep_kernel<<<pgrid, pblk>>>(P);
    defeat_fused_kernel<<<2728, 256>>>(P);
    defeat_finalize_kernel<<<1, 256>>>((float*)d_out);
}

// round 9
// speedup vs baseline: 4.3205x; 1.1793x over previous
#include <cuda_runtime.h>
#include <math.h>
#include <stdint.h>

// DeFeat distillation loss — bf16 mma.sync kernel for all 5 levels + fused finalize.
// adapted = W @ feat_s (+bias); masked squared diff vs feat_t; deterministic reduction.
// B=8, C=256, sizes {128,64,32,16,8}, strides {8..128}, 16 boxes.
//
// Per block: D[256 x 64] = W[256 x 256] * fs[256 x 64]
//   W  pre-packed bf16 [m][k/2] (b32 k-pairs), cp.async double-buffered
//   fs converted fp32->bf16 (round-nearest) in a software-pipelined loader
//   mma.sync.m16n8k8.bf16 — same C layout as R3's verified tf32 path.

#define CC    256
#define NBOX  16
#define BM    256
#define BN    64
#define BK    64
#define KP2   32              // k-pairs per stage
#define NIT   4               // CC / BK
#define ASTR  36              // A smem row stride in b32 (32 data + 4 pad) -> conflict-free
#define BSTR  72              // B smem row stride in b32 (64 data + 8 pad) -> conflict-free

#define A_STAGE_W (BM * ASTR)        // 9216 b32
#define B_STAGE_W (KP2 * BSTR)       // 2304 b32
#define DSMEM_BYTES ((2 * A_STAGE_W + 2 * B_STAGE_W) * 4)   // 92160

#define TOTAL_BLOCKS 2728

__device__ float g_part_gt[2752];
__device__ float g_part_bg[2752];
__device__ unsigned int g_count = 0;
__device__ uint32_t g_Wbf[5][CC * (CC / 2)];   // [lvl][m][kpair] packed bf16x2

struct LevelPtrs { const float *fs, *ft, *Wm, *bias; };
struct KP { LevelPtrs lv[5]; const float* boxes; };

__device__ __forceinline__ void cp16(void* smem_dst, const void* gmem_src) {
    uint32_t d = (uint32_t)__cvta_generic_to_shared(smem_dst);
    asm volatile("cp.async.cg.shared.global [%0], [%1], 16;\n" :: "r"(d), "l"(gmem_src));
}
__device__ __forceinline__ void cp_commit() { asm volatile("cp.async.commit_group;\n"); }
template<int N> __device__ __forceinline__ void cp_wait() { asm volatile("cp.async.wait_group %0;\n" :: "n"(N)); }

// d = {hi = b (odd k), lo = a (even k)}
__device__ __forceinline__ uint32_t packbf(float a, float b) {
    uint32_t r;
    asm("cvt.rn.bf16x2.f32 %0, %1, %2;" : "=r"(r) : "f"(b), "f"(a));
    return r;
}

__device__ __forceinline__ void mma_bf16(float c[4], uint32_t a0, uint32_t a1, uint32_t b0) {
    asm volatile(
        "mma.sync.aligned.m16n8k8.row.col.f32.bf16.bf16.f32 "
        "{%0,%1,%2,%3}, {%4,%5}, {%6}, {%0,%1,%2,%3};\n"
        : "+f"(c[0]), "+f"(c[1]), "+f"(c[2]), "+f"(c[3])
        : "r"(a0), "r"(a1), "r"(b0));
}

// ---- prep: pack W fp32 [m][k] -> bf16x2 [m][k/2]. grid (128,5) x 256 ----
__global__ void defeat_prep_kernel(KP P)
{
    int lvl = blockIdx.y;
    int idx = blockIdx.x * 256 + threadIdx.x;       // 0..32767 (kpair index space)
    const float2 w2 = *(const float2*)(P.lv[lvl].Wm + (size_t)idx * 2);
    g_Wbf[lvl][idx] = packbf(w2.x, w2.y);
}

// ---- main kernel ----
__global__ __launch_bounds__(256, 2)
void defeat_main_kernel(KP P, float* out)
{
    extern __shared__ __align__(16) uint32_t dsmem[];
    uint32_t* Asm = dsmem;                       // 2 stages of A
    uint32_t* Bsm = dsmem + 2 * A_STAGE_W;       // 2 stages of B
    __shared__ float mask_s[BN];
    __shared__ float boxes_s[NBOX * 4];
    __shared__ float red[256];
    __shared__ unsigned s_last;

    const int tid  = threadIdx.x;
    const int warp = tid >> 5, lane = tid & 31;
    const int bid  = blockIdx.x;

    // ---- decode level + tile ----
    int lvl, base;
    if      (bid < 2048) { lvl = 0; base = 0;    }
    else if (bid < 2560) { lvl = 1; base = 2048; }
    else if (bid < 2688) { lvl = 2; base = 2560; }
    else if (bid < 2720) { lvl = 3; base = 2688; }
    else                 { lvl = 4; base = 2720; }

    const int H      = 128 >> lvl;
    const int stride = 8 << lvl;
    const int HW     = H * H;
    const int nTN    = HW >> 6;
    const int rel    = bid - base;
    const int b      = rel / nTN;
    const int nTile  = rel - b * nTN;
    const int posBase = nTile * BN;

    const float* fsb  = P.lv[lvl].fs + (size_t)b * CC * HW;
    const float* ftb  = P.lv[lvl].ft + (size_t)b * CC * HW;
    const float* bias = P.lv[lvl].bias;
    const uint32_t* WbfL = g_Wbf[lvl];

    if (tid < NBOX * 4)
        boxes_s[tid] = P.boxes[(size_t)b * NBOX * 4 + tid];
    __syncthreads();

    // ---- rasterize GT mask for this block's 64 positions ----
    if (tid < BN) {
        int pos = posBase + tid;
        int y = pos / H, x = pos - y * H;
        float m = 0.f;
        float inv = 1.0f / (float)stride;
        #pragma unroll 1
        for (int n = 0; n < NBOX; n++) {
            int lx = min((int)floorf(boxes_s[n*4+0] * inv), H - 1);
            int ly = min((int)floorf(boxes_s[n*4+1] * inv), H - 1);
            int rx = min((int)floorf(boxes_s[n*4+2] * inv), H - 1);
            int ry = min((int)floorf(boxes_s[n*4+3] * inv), H - 1);
            bool hit;
            if (lx == rx || ly == ry) hit = (y == ly) && (x == lx);
            else                      hit = (y >= ly) && (y < ry) && (x >= lx) && (x < rx);
            if (hit) { m = 1.f; break; }
        }
        mask_s[tid] = m;
    }

    // ---- A loader: cp.async, 256 rows x 32 b32 per stage = 2048 x 16B chunks ----
    auto cpA = [&](int it) {
        uint32_t* ab = Asm + (it & 1) * A_STAGE_W;
        const int kp0 = it * KP2;
        #pragma unroll
        for (int i = 0; i < 8; i++) {
            int c = tid + i * 256;
            int m = c >> 3, j = c & 7;
            cp16(ab + m * ASTR + j * 4, WbfL + (size_t)m * (CC / 2) + kp0 + j * 4);
        }
    };

    // ---- B loader: LDG fp32 pairs -> cvt.rn.bf16x2 -> STS. 512 items, 2/thread ----
    float4 br0[2], br1[2];
    auto ldgB = [&](int it) {
        const int k0 = it * BK;
        #pragma unroll
        for (int i = 0; i < 2; i++) {
            int w2 = tid + i * 256;
            int kp = w2 >> 4, j = w2 & 15;
            const float* p0 = fsb + (size_t)(k0 + 2 * kp) * HW + posBase + j * 4;
            br0[i] = *(const float4*)p0;
            br1[i] = *(const float4*)(p0 + HW);
        }
    };
    auto stsB = [&](int it) {
        uint32_t* bb = Bsm + (it & 1) * B_STAGE_W;
        #pragma unroll
        for (int i = 0; i < 2; i++) {
            int w2 = tid + i * 256;
            int kp = w2 >> 4, j = w2 & 15;
            uint4 u;
            u.x = packbf(br0[i].x, br1[i].x);
            u.y = packbf(br0[i].y, br1[i].y);
            u.z = packbf(br0[i].z, br1[i].z);
            u.w = packbf(br0[i].w, br1[i].w);
            *(uint4*)(bb + kp * BSTR + j * 4) = u;
        }
    };

    // ---- warp layout: 8 warps = 4(m) x 2(n); warp tile 64m x 32n ----
    const int wm = warp >> 1, wn = warp & 1;
    const int gid = lane >> 2, tg = lane & 3;
    const int M0 = wm * 64;
    const int N0 = wn * 32;

    float acc[4][4][4];
    #pragma unroll
    for (int mt = 0; mt < 4; mt++)
        #pragma unroll
        for (int nt = 0; nt < 4; nt++)
            #pragma unroll
            for (int r = 0; r < 4; r++) acc[mt][nt][r] = 0.f;

    // ---- prologue ----
    cpA(0); cp_commit();
    ldgB(0);
    cpA(1); cp_commit();
    stsB(0);
    cp_wait<1>();           // A(0) done; A(1) in flight
    __syncthreads();

    // ---- main loop ----
    for (int it = 0; it < NIT; it++) {
        const uint32_t* ab = Asm + (it & 1) * A_STAGE_W;
        const uint32_t* bb = Bsm + (it & 1) * B_STAGE_W;

        if (it + 1 < NIT) ldgB(it + 1);

        #pragma unroll
        for (int s = 0; s < 8; s++) {
            const int qb = s * 4;
            uint32_t afr[4][2], bfr[4];
            #pragma unroll
            for (int mt = 0; mt < 4; mt++) {
                int mr = M0 + mt * 16 + gid;
                afr[mt][0] = ab[(mr    ) * ASTR + qb + tg];
                afr[mt][1] = ab[(mr + 8) * ASTR + qb + tg];
            }
            #pragma unroll
            for (int nt = 0; nt < 4; nt++)
                bfr[nt] = bb[(qb + tg) * BSTR + N0 + nt * 8 + gid];
            #pragma unroll
            for (int mt = 0; mt < 4; mt++)
                #pragma unroll
                for (int nt = 0; nt < 4; nt++)
                    mma_bf16(acc[mt][nt], afr[mt][0], afr[mt][1], bfr[nt]);
        }

        if (it + 1 < NIT) {
            stsB(it + 1);                          // other buffer: safe (synced last iter)
            if (it + 2 < NIT) { cpA(it + 2); cp_commit(); cp_wait<1>(); }
            else              { cp_wait<0>(); }
        }
        __syncthreads();
    }

    // ---- epilogue: masked squared diff vs feat_t (same layout as verified tf32) ----
    float sgt = 0.f, sbg = 0.f;
    #pragma unroll
    for (int mt = 0; mt < 4; mt++) {
        #pragma unroll
        for (int h = 0; h < 2; h++) {
            int row = M0 + mt * 16 + gid + 8 * h;
            float bv = bias[row];
            #pragma unroll
            for (int nt = 0; nt < 4; nt++) {
                int colL = N0 + nt * 8 + 2 * tg;
                float2 t2 = *(const float2*)&ftb[(size_t)row * HW + posBase + colL];
                float a0 = acc[mt][nt][2*h + 0] + bv;
                float a1 = acc[mt][nt][2*h + 1] + bv;
                float d0 = t2.x - a0, d1 = t2.y - a1;
                float m0 = mask_s[colL], m1 = mask_s[colL + 1];
                float q0 = d0 * d0, q1 = d1 * d1;
                sgt += q0 * m0 + q1 * m1;
                sbg += q0 * (1.f - m0) + q1 * (1.f - m1);
            }
        }
    }

    // ---- deterministic block reduction ----
    #pragma unroll
    for (int off = 16; off > 0; off >>= 1) {
        sgt += __shfl_down_sync(0xffffffffu, sgt, off);
        sbg += __shfl_down_sync(0xffffffffu, sbg, off);
    }
    if (lane == 0) { red[warp] = sgt; red[warp + 8] = sbg; }
    __syncthreads();
    if (tid == 0) {
        float g = 0.f, bg = 0.f;
        #pragma unroll
        for (int w2 = 0; w2 < 8; w2++) { g += red[w2]; bg += red[w2 + 8]; }
        g_part_gt[bid] = g;
        g_part_bg[bid] = bg;
        __threadfence();
        unsigned t = atomicAdd(&g_count, 1u);
        s_last = (t == TOTAL_BLOCKS - 1) ? 1u : 0u;
    }
    __syncthreads();

    // ---- last block: deterministic finalize ----
    if (s_last) {
        __threadfence();
        const int counts[5] = {2048, 512, 128, 32, 8};
        float loss = 0.f;
        int off = 0;
        for (int L = 0; L < 5; L++) {
            float g = 0.f, bg = 0.f;
            for (int i = tid; i < counts[L]; i += 256) g  += g_part_gt[off + i];
            for (int i = tid; i < counts[L]; i += 256) bg += g_part_bg[off + i];

            red[tid] = g; __syncthreads();
            for (int s = 128; s > 0; s >>= 1) { if (tid < s) red[tid] += red[tid + s]; __syncthreads(); }
            float gs = red[0]; __syncthreads();

            red[tid] = bg; __syncthreads();
            for (int s = 128; s > 0; s >>= 1) { if (tid < s) red[tid] += red[tid + s]; __syncthreads(); }
            float bgs = red[0]; __syncthreads();

            loss += 0.004f * sqrtf(gs + 1e-8f) + 0.0002f * sqrtf(bgs + 1e-8f);
            off += counts[L];
            __syncthreads();
        }
        if (tid == 0) {
            out[0] = loss;
            g_count = 0;     // reset for next graph replay
        }
    }
}

extern "C" void kernel_launch(void* const* d_in, const int* in_sizes, int n_in,
                              void* d_out, int out_size)
{
    (void)in_sizes; (void)n_in; (void)out_size;
    KP P;
    for (int i = 0; i < 5; i++) {
        P.lv[i].fs   = (const float*)d_in[4 * i + 0];
        P.lv[i].ft   = (const float*)d_in[4 * i + 1];
        P.lv[i].Wm   = (const float*)d_in[4 * i + 2];
        P.lv[i].bias = (const float*)d_in[4 * i + 3];
    }
    P.boxes = (const float*)d_in[20];

    dim3 pg(128, 5);
    defeat_prep_kernel<<<pg, 256>>>(P);

    cudaFuncSetAttribute(defeat_main_kernel,
                         cudaFuncAttributeMaxDynamicSharedMemorySize, DSMEM_BYTES);
    defeat_main_kernel<<<TOTAL_BLOCKS, 256, DSMEM_BYTES>>>(P, (float*)d_out);
}

// round 10
// speedup vs baseline: 5.3041x; 1.2277x over previous
#include <cuda_runtime.h>
#include <math.h>
#include <stdint.h>

// DeFeat distillation loss — bf16 m16n8k16 mma.sync kernel, all 5 levels + fused finalize.
// adapted = W @ feat_s (+bias); masked squared diff vs feat_t; deterministic reduction.
// B=8, C=256, sizes {128,64,32,16,8}, strides {8..128}, 16 boxes.
//
// Per block: D[256 x 64] = W[256 x 256] * fs[256 x 64]
//   W  pre-packed bf16 [m][k/2] (b32 k-pairs), cp.async double-buffered
//   fs converted fp32->bf16 (round-nearest) in a software-pipelined loader
//   A fragments via ldmatrix.x4; mma.sync.m16n8k16.bf16 (C layout == verified k8 path).

#define CC    256
#define NBOX  16
#define BM    256
#define BN    64
#define BK    64
#define KP2   32              // k-pairs per stage
#define NIT   4               // CC / BK
#define ASTR  36              // A smem row stride in b32 (32 data + 4 pad)
#define BSTR  72              // B smem row stride in b32 (64 data + 8 pad)

#define A_STAGE_W (BM * ASTR)        // 9216 b32
#define B_STAGE_W (KP2 * BSTR)       // 2304 b32
#define DSMEM_BYTES ((2 * A_STAGE_W + 2 * B_STAGE_W) * 4)   // 92160

#define TOTAL_BLOCKS 2728

__device__ float g_part_gt[2752];
__device__ float g_part_bg[2752];
__device__ unsigned int g_count = 0;
__device__ uint32_t g_Wbf[5][CC * (CC / 2)];   // [lvl][m][kpair] packed bf16x2

struct LevelPtrs { const float *fs, *ft, *Wm, *bias; };
struct KP { LevelPtrs lv[5]; const float* boxes; };

__device__ __forceinline__ uint32_t smem_u32(const void* p) {
    uint32_t a;
    asm("{ .reg .u64 t; cvta.to.shared.u64 t, %1; cvt.u32.u64 %0, t; }" : "=r"(a) : "l"(p));
    return a;
}
__device__ __forceinline__ void cp16(void* smem_dst, const void* gmem_src) {
    uint32_t d = (uint32_t)__cvta_generic_to_shared(smem_dst);
    asm volatile("cp.async.cg.shared.global [%0], [%1], 16;\n" :: "r"(d), "l"(gmem_src));
}
__device__ __forceinline__ void cp_commit() { asm volatile("cp.async.commit_group;\n"); }
template<int N> __device__ __forceinline__ void cp_wait() { asm volatile("cp.async.wait_group %0;\n" :: "n"(N)); }

// d = {hi = b (odd k), lo = a (even k)}
__device__ __forceinline__ uint32_t packbf(float a, float b) {
    uint32_t r;
    asm("cvt.rn.bf16x2.f32 %0, %1, %2;" : "=r"(r) : "f"(b), "f"(a));
    return r;
}

__device__ __forceinline__ void ldmx4(uint32_t r[4], uint32_t addr) {
    asm volatile("ldmatrix.sync.aligned.m8n8.x4.shared.b16 {%0,%1,%2,%3}, [%4];"
        : "=r"(r[0]), "=r"(r[1]), "=r"(r[2]), "=r"(r[3]) : "r"(addr));
}

__device__ __forceinline__ void mma_k16(float c[4], const uint32_t a[4],
                                        uint32_t b0, uint32_t b1) {
    asm volatile(
        "mma.sync.aligned.m16n8k16.row.col.f32.bf16.bf16.f32 "
        "{%0,%1,%2,%3}, {%4,%5,%6,%7}, {%8,%9}, {%0,%1,%2,%3};\n"
        : "+f"(c[0]), "+f"(c[1]), "+f"(c[2]), "+f"(c[3])
        : "r"(a[0]), "r"(a[1]), "r"(a[2]), "r"(a[3]), "r"(b0), "r"(b1));
}

// ---- prep: pack W fp32 [m][k] -> bf16x2 [m][k/2]. grid (128,5) x 256 ----
__global__ void defeat_prep_kernel(KP P)
{
    int lvl = blockIdx.y;
    int idx = blockIdx.x * 256 + threadIdx.x;       // kpair index
    const float2 w2 = *(const float2*)(P.lv[lvl].Wm + (size_t)idx * 2);
    g_Wbf[lvl][idx] = packbf(w2.x, w2.y);
}

// ---- main kernel ----
__global__ __launch_bounds__(256, 2)
void defeat_main_kernel(KP P, float* out)
{
    extern __shared__ __align__(16) uint32_t dsmem[];
    uint32_t* Asm = dsmem;                       // 2 stages of A
    uint32_t* Bsm = dsmem + 2 * A_STAGE_W;       // 2 stages of B
    __shared__ float mask_s[BN];
    __shared__ float boxes_s[NBOX * 4];
    __shared__ float red[256];
    __shared__ unsigned s_last;

    const int tid  = threadIdx.x;
    const int warp = tid >> 5, lane = tid & 31;
    const int bid  = blockIdx.x;

    // ---- decode level + tile ----
    int lvl, base;
    if      (bid < 2048) { lvl = 0; base = 0;    }
    else if (bid < 2560) { lvl = 1; base = 2048; }
    else if (bid < 2688) { lvl = 2; base = 2560; }
    else if (bid < 2720) { lvl = 3; base = 2688; }
    else                 { lvl = 4; base = 2720; }

    const int H      = 128 >> lvl;
    const int stride = 8 << lvl;
    const int HW     = H * H;
    const int nTN    = HW >> 6;
    const int rel    = bid - base;
    const int b      = rel / nTN;
    const int nTile  = rel - b * nTN;
    const int posBase = nTile * BN;

    const float* fsb  = P.lv[lvl].fs + (size_t)b * CC * HW;
    const float* ftb  = P.lv[lvl].ft + (size_t)b * CC * HW;
    const float* bias = P.lv[lvl].bias;
    const uint32_t* WbfL = g_Wbf[lvl];

    if (tid < NBOX * 4)
        boxes_s[tid] = P.boxes[(size_t)b * NBOX * 4 + tid];
    __syncthreads();

    // ---- rasterize GT mask for this block's 64 positions ----
    if (tid < BN) {
        int pos = posBase + tid;
        int y = pos / H, x = pos - y * H;
        float m = 0.f;
        float inv = 1.0f / (float)stride;
        #pragma unroll 1
        for (int n = 0; n < NBOX; n++) {
            int lx = min((int)floorf(boxes_s[n*4+0] * inv), H - 1);
            int ly = min((int)floorf(boxes_s[n*4+1] * inv), H - 1);
            int rx = min((int)floorf(boxes_s[n*4+2] * inv), H - 1);
            int ry = min((int)floorf(boxes_s[n*4+3] * inv), H - 1);
            bool hit;
            if (lx == rx || ly == ry) hit = (y == ly) && (x == lx);
            else                      hit = (y >= ly) && (y < ry) && (x >= lx) && (x < rx);
            if (hit) { m = 1.f; break; }
        }
        mask_s[tid] = m;
    }

    // ---- A loader: cp.async, 256 rows x 32 b32 per stage ----
    auto cpA = [&](int it) {
        uint32_t* ab = Asm + (it & 1) * A_STAGE_W;
        const int kp0 = it * KP2;
        #pragma unroll
        for (int i = 0; i < 8; i++) {
            int c = tid + i * 256;
            int m = c >> 3, j = c & 7;
            cp16(ab + m * ASTR + j * 4, WbfL + (size_t)m * (CC / 2) + kp0 + j * 4);
        }
    };

    // ---- B loader: LDG fp32 pairs -> cvt.rn.bf16x2 -> STS ----
    float4 br0[2], br1[2];
    auto ldgB = [&](int it) {
        const int k0 = it * BK;
        #pragma unroll
        for (int i = 0; i < 2; i++) {
            int w2 = tid + i * 256;
            int kp = w2 >> 4, j = w2 & 15;
            const float* p0 = fsb + (size_t)(k0 + 2 * kp) * HW + posBase + j * 4;
            br0[i] = *(const float4*)p0;
            br1[i] = *(const float4*)(p0 + HW);
        }
    };
    auto stsB = [&](int it) {
        uint32_t* bb = Bsm + (it & 1) * B_STAGE_W;
        #pragma unroll
        for (int i = 0; i < 2; i++) {
            int w2 = tid + i * 256;
            int kp = w2 >> 4, j = w2 & 15;
            uint4 u;
            u.x = packbf(br0[i].x, br1[i].x);
            u.y = packbf(br0[i].y, br1[i].y);
            u.z = packbf(br0[i].z, br1[i].z);
            u.w = packbf(br0[i].w, br1[i].w);
            *(uint4*)(bb + kp * BSTR + j * 4) = u;
        }
    };

    // ---- warp layout: 8 warps = 4(m) x 2(n); warp tile 64m x 32n ----
    const int wm = warp >> 1, wn = warp & 1;
    const int gid = lane >> 2, tg = lane & 3;
    const int M0 = wm * 64;
    const int N0 = wn * 32;

    // ldmatrix lane address: rows M0+mt*16+(lane&15), k-half (lane>>4)*4 kpairs
    const uint32_t asm_u32 = smem_u32(Asm);
    const uint32_t a_lane_off = (uint32_t)(((M0 + (lane & 15)) * ASTR + ((lane >> 4) << 2)) * 4);

    float acc[4][4][4];
    #pragma unroll
    for (int mt = 0; mt < 4; mt++)
        #pragma unroll
        for (int nt = 0; nt < 4; nt++)
            #pragma unroll
            for (int r = 0; r < 4; r++) acc[mt][nt][r] = 0.f;

    // ---- prologue ----
    cpA(0); cp_commit();
    ldgB(0);
    cpA(1); cp_commit();
    stsB(0);
    cp_wait<1>();           // A(0) done; A(1) in flight
    __syncthreads();

    // ---- main loop ----
    for (int it = 0; it < NIT; it++) {
        const uint32_t abase = asm_u32 + (uint32_t)((it & 1) * A_STAGE_W * 4);
        const uint32_t* bb = Bsm + (it & 1) * B_STAGE_W;

        if (it + 1 < NIT) ldgB(it + 1);

        #pragma unroll
        for (int s = 0; s < 4; s++) {               // k16 steps; qb in kpair units
            const int qb = s * 8;
            uint32_t afr[4][4], bfr[4][2];
            #pragma unroll
            for (int mt = 0; mt < 4; mt++)
                ldmx4(afr[mt], abase + a_lane_off + (uint32_t)((mt * 16 * ASTR + qb) * 4));
            #pragma unroll
            for (int nt = 0; nt < 4; nt++) {
                int nc = N0 + nt * 8 + gid;
                bfr[nt][0] = bb[(qb + tg    ) * BSTR + nc];
                bfr[nt][1] = bb[(qb + tg + 4) * BSTR + nc];
            }
            #pragma unroll
            for (int mt = 0; mt < 4; mt++)
                #pragma unroll
                for (int nt = 0; nt < 4; nt++)
                    mma_k16(acc[mt][nt], afr[mt], bfr[nt][0], bfr[nt][1]);
        }

        if (it + 1 < NIT) {
            stsB(it + 1);
            if (it + 2 < NIT) { cpA(it + 2); cp_commit(); cp_wait<1>(); }
            else              { cp_wait<0>(); }
        }
        __syncthreads();
    }

    // ---- epilogue: masked squared diff vs feat_t ----
    float sgt = 0.f, sbg = 0.f;
    #pragma unroll
    for (int mt = 0; mt < 4; mt++) {
        #pragma unroll
        for (int h = 0; h < 2; h++) {
            int row = M0 + mt * 16 + gid + 8 * h;
            float bv = bias[row];
            #pragma unroll
            for (int nt = 0; nt < 4; nt++) {
                int colL = N0 + nt * 8 + 2 * tg;
                float2 t2 = *(const float2*)&ftb[(size_t)row * HW + posBase + colL];
                float a0 = acc[mt][nt][2*h + 0] + bv;
                float a1 = acc[mt][nt][2*h + 1] + bv;
                float d0 = t2.x - a0, d1 = t2.y - a1;
                float m0 = mask_s[colL], m1 = mask_s[colL + 1];
                float q0 = d0 * d0, q1 = d1 * d1;
                sgt += q0 * m0 + q1 * m1;
                sbg += q0 * (1.f - m0) + q1 * (1.f - m1);
            }
        }
    }

    // ---- deterministic block reduction ----
    #pragma unroll
    for (int off = 16; off > 0; off >>= 1) {
        sgt += __shfl_down_sync(0xffffffffu, sgt, off);
        sbg += __shfl_down_sync(0xffffffffu, sbg, off);
    }
    if (lane == 0) { red[warp] = sgt; red[warp + 8] = sbg; }
    __syncthreads();
    if (tid == 0) {
        float g = 0.f, bg = 0.f;
        #pragma unroll
        for (int w2 = 0; w2 < 8; w2++) { g += red[w2]; bg += red[w2 + 8]; }
        g_part_gt[bid] = g;
        g_part_bg[bid] = bg;
        __threadfence();
        unsigned t = atomicAdd(&g_count, 1u);
        s_last = (t == TOTAL_BLOCKS - 1) ? 1u : 0u;
    }
    __syncthreads();

    // ---- last block: deterministic finalize ----
    if (s_last) {
        __threadfence();
        const int counts[5] = {2048, 512, 128, 32, 8};
        float loss = 0.f;
        int off = 0;
        for (int L = 0; L < 5; L++) {
            float g = 0.f, bg = 0.f;
            for (int i = tid; i < counts[L]; i += 256) g  += g_part_gt[off + i];
            for (int i = tid; i < counts[L]; i += 256) bg += g_part_bg[off + i];

            red[tid] = g; __syncthreads();
            for (int s = 128; s > 0; s >>= 1) { if (tid < s) red[tid] += red[tid + s]; __syncthreads(); }
            float gs = red[0]; __syncthreads();

            red[tid] = bg; __syncthreads();
            for (int s = 128; s > 0; s >>= 1) { if (tid < s) red[tid] += red[tid + s]; __syncthreads(); }
            float bgs = red[0]; __syncthreads();

            loss += 0.004f * sqrtf(gs + 1e-8f) + 0.0002f * sqrtf(bgs + 1e-8f);
            off += counts[L];
            __syncthreads();
        }
        if (tid == 0) {
            out[0] = loss;
            g_count = 0;     // reset for next graph replay
        }
    }
}

extern "C" void kernel_launch(void* const* d_in, const int* in_sizes, int n_in,
                              void* d_out, int out_size)
{
    (void)in_sizes; (void)n_in; (void)out_size;
    KP P;
    for (int i = 0; i < 5; i++) {
        P.lv[i].fs   = (const float*)d_in[4 * i + 0];
        P.lv[i].ft   = (const float*)d_in[4 * i + 1];
        P.lv[i].Wm   = (const float*)d_in[4 * i + 2];
        P.lv[i].bias = (const float*)d_in[4 * i + 3];
    }
    P.boxes = (const float*)d_in[20];

    dim3 pg(128, 5);
    defeat_prep_kernel<<<pg, 256>>>(P);

    cudaFuncSetAttribute(defeat_main_kernel,
                         cudaFuncAttributeMaxDynamicSharedMemorySize, DSMEM_BYTES);
    defeat_main_kernel<<<TOTAL_BLOCKS, 256, DSMEM_BYTES>>>(P, (float*)d_out);
}